// round 15
// baseline (speedup 1.0000x reference)
#include <cuda_runtime.h>
#include <cuda_bf16.h>
#include <cstdint>

// Problem constants
#define NPATCH   32768      // 128 batch * 16*16 patches
#define DDIM     256        // 16 channels * 4*4 patch
#define KCODES   1024
// 1/(2*variance) with variance = -(256 / (2*ln 0.1))  =>  inv2var = ln(10)/256
#define INV2VAR  0.0089944730195076785f
#define SLOTS    28
#define TH_COLLECT 8e-4f    // collection window vs (possibly stale) max
#define TH_FINAL   5e-4f    // refilter window vs final max

// Scratch (static device globals; no runtime allocation)
__device__ __nv_bfloat16  g_cb16  [KCODES * DDIM];
__device__ float          g_cnorm [KCODES];
__device__ float          g_smooth[KCODES * DDIM];
__device__ int            g_bmu   [NPATCH];

// ---- bit-cast helper ------------------------------------------------------
__device__ __forceinline__ uint32_t bf2_bits(__nv_bfloat162 v) {
    union { __nv_bfloat162 h; uint32_t u; } cv;
    cv.h = v;
    return cv.u;
}

// ---- monotone float<->uint encoding for atomicMax over floats -------------
__device__ __forceinline__ unsigned encf(float f) {
    unsigned u = __float_as_uint(f);
    return (u & 0x80000000u) ? ~u : (u | 0x80000000u);
}
__device__ __forceinline__ float decf(unsigned u) {
    u = (u & 0x80000000u) ? (u & 0x7fffffffu) : ~u;
    return __uint_as_float(u);
}

// ---- async copy -----------------------------------------------------------
__device__ __forceinline__ void cp_async16(uint32_t saddr, const void* gptr) {
    asm volatile("cp.async.cg.shared.global [%0], [%1], 16;"
                 :: "r"(saddr), "l"(gptr) : "memory");
}
__device__ __forceinline__ void cp_commit() {
    asm volatile("cp.async.commit_group;" ::: "memory");
}
__device__ __forceinline__ void cp_wait1() {
    asm volatile("cp.async.wait_group 1;" ::: "memory");
}

// ---- tensor-core primitives ----------------------------------------------
__device__ __forceinline__ void ldsm_x4(uint32_t (&r)[4], uint32_t saddr) {
    asm volatile("ldmatrix.sync.aligned.m8n8.x4.shared.b16 {%0,%1,%2,%3}, [%4];"
                 : "=r"(r[0]), "=r"(r[1]), "=r"(r[2]), "=r"(r[3]) : "r"(saddr));
}
__device__ __forceinline__ void mma_bf16(float (&d)[4], const uint32_t (&a)[4],
                                         uint32_t b0, uint32_t b1) {
    asm volatile("mma.sync.aligned.m16n8k16.row.col.f32.bf16.bf16.f32 "
                 "{%0,%1,%2,%3}, {%4,%5,%6,%7}, {%8,%9}, {%0,%1,%2,%3};"
                 : "+f"(d[0]), "+f"(d[1]), "+f"(d[2]), "+f"(d[3])
                 : "r"(a[0]), "r"(a[1]), "r"(a[2]), "r"(a[3]), "r"(b0), "r"(b1));
}

// XOR swizzle for 64B-row smem tiles: chunk' = chunk ^ ((row>>1)&3).
__device__ __forceinline__ uint32_t sw_off(int row, int chunk) {
    return (uint32_t)(row * 64 + ((chunk ^ ((row >> 1) & 3)) << 4));
}

// dynamic-smem layout for k_prune (bytes)
#define SM_XS     0          // [8][128*32] bf16  = 65536
#define SM_CS     65536      // [3][128*32] bf16  = 24576 -> 90112
#define SM_CN     90112      // float[128]     -> 90624
#define SM_MAX    90624      // unsigned[128]  -> 91136
#define SM_CNT    91136      // int[128]       -> 91648
#define SM_SLOTV  91648      // float[128*28] = 14336 -> 105984
#define SM_SLOTC  105984     // short[128*28] =  7168 -> 113152
#define SM_Q      113152     // int[128]       -> 113664
#define SM_QN     113664     // int[2]         -> 113672
#define SM_XN     113680     // float[128]     -> 114192
#define SM_TOTAL  114304

// ---------------------------------------------------------------------------
// K0: codebook prep.
// Blocks [0,128): cnorm + bf16 copy (one warp per row).
// Blocks [128,384): Gaussian-smoothed codebook (4 rows/block, radius-64),
//   unrolled x4 for memory-level parallelism.
// ---------------------------------------------------------------------------
__global__ void k_prep(const float* __restrict__ cb) {
    int tid = threadIdx.x;
    if (blockIdx.x < 128) {
        int row  = blockIdx.x * 8 + (tid >> 5);
        int lane = tid & 31;
        const float* p = cb + row * DDIM;
        float s = 0.0f;
        #pragma unroll
        for (int j = 0; j < DDIM / 32; ++j) {
            float v = p[lane + j * 32];
            g_cb16[row * DDIM + lane + j * 32] = __float2bfloat16(v);
            s = fmaf(v, v, s);
        }
        #pragma unroll
        for (int o = 16; o; o >>= 1) s += __shfl_xor_sync(0xffffffffu, s, o);
        if (lane == 0) g_cnorm[row] = s;
    } else {
        __shared__ float wd[136];
        int jbase = (blockIdx.x - 128) * 4;
        if (tid < 136) {
            float dd = (float)(tid - 67);
            wd[tid] = expf(-(dd * dd) * INV2VAR);
        }
        __syncthreads();
        float acc[4] = {0.f, 0.f, 0.f, 0.f};
        int klo = jbase - 64;      if (klo < 0) klo = 0;
        int khi = jbase + 3 + 64;  if (khi > KCODES - 1) khi = KCODES - 1;
        int kk = klo;
        for (; kk + 3 <= khi; kk += 4) {       // 4 loads in flight
            float v0 = cb[(kk + 0) * DDIM + tid];
            float v1 = cb[(kk + 1) * DDIM + tid];
            float v2 = cb[(kk + 2) * DDIM + tid];
            float v3 = cb[(kk + 3) * DDIM + tid];
            int b0 = kk - jbase + 67;
            #pragma unroll
            for (int t = 0; t < 4; ++t) {
                float a = acc[t];
                a = fmaf(wd[b0 - t],     v0, a);
                a = fmaf(wd[b0 + 1 - t], v1, a);
                a = fmaf(wd[b0 + 2 - t], v2, a);
                a = fmaf(wd[b0 + 3 - t], v3, a);
                acc[t] = a;
            }
        }
        for (; kk <= khi; ++kk) {
            float v = cb[kk * DDIM + tid];
            int base = kk - jbase + 67;
            #pragma unroll
            for (int t = 0; t < 4; ++t)
                acc[t] = fmaf(wd[base - t], v, acc[t]);
        }
        #pragma unroll
        for (int t = 0; t < 4; ++t)
            g_smooth[(jbase + t) * DDIM + tid] = acc[t];
    }
}

// ---------------------------------------------------------------------------
// K1: fused patchify + prune + refilter + exact rescore.
// X tile read from x (fp32 NCHW) once -> bf16 swizzled smem; xnorm fused.
// C slabs stream via cp.async, 3 buffers, 2-slab lookahead, 1 barrier/slab.
// Phase A: bf16 MMA (acc init -cnorm/2 => acc = dot' = s - cn/2);
//   candidates within TH_COLLECT of max(stale chunk-max, local 64-code max)
//   (any estimate <= final max preserves the TH_FINAL superset guarantee).
// Phase B: refilter vs FINAL max (TH_FINAL); single survivor -> bmu; else
//   smem work queue, load-balanced exact fp32 rescore (reference rounding
//   chain fl(fl(xn-2s)+cn) + lowest-code tie-break).
// ---------------------------------------------------------------------------
__global__ __launch_bounds__(256, 2) void k_prune(const float* __restrict__ x,
                                                  const float* __restrict__ cb) {
    extern __shared__ char smem_raw[];
    __nv_bfloat16* Xs    = (__nv_bfloat16*)(smem_raw + SM_XS);
    __nv_bfloat16* Cs    = (__nv_bfloat16*)(smem_raw + SM_CS);
    float*    cn_sh  = (float*)   (smem_raw + SM_CN);
    unsigned* smax   = (unsigned*)(smem_raw + SM_MAX);
    int*      cnt    = (int*)     (smem_raw + SM_CNT);
    float*    slot_v = (float*)   (smem_raw + SM_SLOTV);
    short*    slot_c = (short*)   (smem_raw + SM_SLOTC);
    int*      queue  = (int*)     (smem_raw + SM_Q);
    int*      qn     = (int*)     (smem_raw + SM_QN);   // [0]=count, [1]=head
    float*    xn_sh  = (float*)   (smem_raw + SM_XN);

    int tid  = threadIdx.x;
    int lane = tid & 31;
    int wid  = tid >> 5;
    int wm   = wid & 3;            // m band: 32 rows
    int wn   = wid >> 2;           // n band: 64 codes
    int m0   = blockIdx.x * 128;

    if (tid < 128) { smax[tid] = 0u; cnt[tid] = 0; cn_sh[tid] = g_cnorm[tid]; }
    if (tid == 0) { qn[0] = 0; qn[1] = 0; }

    uint32_t xs_base = (uint32_t)__cvta_generic_to_shared(Xs);
    uint32_t cs_base = (uint32_t)__cvta_generic_to_shared(Cs);

    // ---- C streaming addresses: 2 x 16B per thread per slab ----
    int r0 = tid >> 2,  g0 = tid & 3;
    int r1 = r0 + 64;
    uint32_t so0 = sw_off(r0, g0), so1 = sw_off(r1, g0);

    auto issueC = [&](int ls) {                 // slab ls -> buffer ls%3
        int k0 = (ls & 7) * 32;
        int n0 = (ls >> 3) << 7;
        uint32_t cbuf = cs_base + (uint32_t)((ls % 3) * 8192);
        cp_async16(cbuf + so0, &g_cb16[(n0 + r0) * DDIM + k0 + g0 * 8]);
        cp_async16(cbuf + so1, &g_cb16[(n0 + r1) * DDIM + k0 + g0 * 8]);
        cp_commit();
    };

    // prologue: slabs 0 and 1 in flight
    issueC(0);
    issueC(1);

    // ---- fused patchify: x fp32 -> bf16 Xs + xnorm (overlaps cp.async) ----
    #pragma unroll
    for (int i = 0; i < 16; ++i) {
        int row = i * 8 + wid;
        int m   = m0 + row;
        int n = m >> 8, rem = m & 255;
        int ph = rem >> 4, pw = rem & 15;
        int c = lane >> 1, pyb = (lane & 1) << 1;      // dims lane*8 .. +7
        const float* xb = &x[(((n * 16 + c) * 64 + ph * 4 + pyb) * 64 + pw * 4)];
        float4 a = *(const float4*)xb;
        float4 b = *(const float4*)(xb + 64);
        uint4 pk;
        pk.x = bf2_bits(__floats2bfloat162_rn(a.x, a.y));
        pk.y = bf2_bits(__floats2bfloat162_rn(a.z, a.w));
        pk.z = bf2_bits(__floats2bfloat162_rn(b.x, b.y));
        pk.w = bf2_bits(__floats2bfloat162_rn(b.z, b.w));
        int slab = lane >> 2, chunk = lane & 3;
        *(uint4*)((char*)Xs + slab * 8192 + sw_off(row, chunk)) = pk;
        float s = fmaf(a.x, a.x, fmaf(a.y, a.y, fmaf(a.z, a.z, a.w * a.w)));
        s = fmaf(b.x, b.x, fmaf(b.y, b.y, fmaf(b.z, b.z, fmaf(b.w, b.w, s))));
        #pragma unroll
        for (int o = 16; o; o >>= 1) s += __shfl_xor_sync(0xffffffffu, s, o);
        if (lane == 0) xn_sh[row] = s;
    }

    // LDSM invariants
    int arow[2], brow[4];
    #pragma unroll
    for (int mt = 0; mt < 2; ++mt) arow[mt] = wm * 32 + mt * 16 + (lane & 15);
    #pragma unroll
    for (int nt = 0; nt < 4; ++nt) brow[nt] = wn * 64 + nt * 16 + (lane & 15);
    int ch_hi = lane >> 4;

    float acc[2][8][4];

    for (int ls = 0; ls < 64; ++ls) {
        int s = ls & 7;
        cp_wait1();                    // slab ls landed (<=1 group outstanding)
        __syncthreads();               // publish slab ls (and X/init on ls==0)
        if (ls < 62) issueC(ls + 2);   // buffer (ls+2)%3 free since iter ls-1
        if (s == 0) {
            #pragma unroll
            for (int nt = 0; nt < 8; ++nt)
                #pragma unroll
                for (int z = 0; z < 4; ++z) {
                    int nloc = wn * 64 + nt * 8 + 2 * (lane & 3) + (z & 1);
                    float v = -0.5f * cn_sh[nloc];
                    acc[0][nt][z] = v;
                    acc[1][nt][z] = v;
                }
        }

        uint32_t xslab = xs_base + (uint32_t)(s * 8192);
        uint32_t cslab = cs_base + (uint32_t)((ls % 3) * 8192);
        #pragma unroll
        for (int kstep = 0; kstep < 2; ++kstep) {
            int kc = kstep * 2 + ch_hi;
            uint32_t a[2][4];
            #pragma unroll
            for (int mt = 0; mt < 2; ++mt)
                ldsm_x4(a[mt], xslab + sw_off(arow[mt], kc));
            #pragma unroll
            for (int ntp = 0; ntp < 4; ++ntp) {
                uint32_t b[4];
                ldsm_x4(b, cslab + sw_off(brow[ntp], kc));
                #pragma unroll
                for (int mt = 0; mt < 2; ++mt) {
                    mma_bf16(acc[mt][2 * ntp + 0], a[mt], b[0], b[2]);
                    mma_bf16(acc[mt][2 * ntp + 1], a[mt], b[1], b[3]);
                }
            }
        }

        if (s == 7) {
            int nchunk0 = (ls >> 3) << 7;
            // ---- epilogue (no intra-chunk barrier):
            // local 64-code max -> atomicMax; collect vs
            // max(stale shared max, local max) - TH_COLLECT (superset-safe).
            #pragma unroll
            for (int mt = 0; mt < 2; ++mt)
                #pragma unroll
                for (int h = 0; h < 2; ++h) {
                    int mloc = wm * 32 + mt * 16 + (lane >> 2) + 8 * h;
                    float mv = acc[mt][0][2 * h];
                    #pragma unroll
                    for (int nt = 0; nt < 8; ++nt) {
                        mv = fmaxf(mv, acc[mt][nt][2 * h + 0]);
                        mv = fmaxf(mv, acc[mt][nt][2 * h + 1]);
                    }
                    mv = fmaxf(mv, __shfl_xor_sync(0xffffffffu, mv, 1));
                    mv = fmaxf(mv, __shfl_xor_sync(0xffffffffu, mv, 2));
                    if ((lane & 3) == 0) atomicMax(&smax[mloc], encf(mv));
                    float lim = fmaxf(decf(smax[mloc]), mv) - TH_COLLECT;
                    #pragma unroll
                    for (int nt = 0; nt < 8; ++nt)
                        #pragma unroll
                        for (int col = 0; col < 2; ++col) {
                            float v = acc[mt][nt][2 * h + col];
                            if (v >= lim) {
                                int code = nchunk0 + wn * 64 + nt * 8 + 2 * (lane & 3) + col;
                                int p = atomicAdd(&cnt[mloc], 1);
                                if (p < SLOTS) {
                                    slot_v[mloc * SLOTS + p] = v;
                                    slot_c[mloc * SLOTS + p] = (short)code;
                                }
                            }
                        }
                }
            // prefetch next chunk's cnorm (ordered by next top-of-loop sync)
            if (ls < 63 && tid < 128) cn_sh[tid] = g_cnorm[nchunk0 + 128 + tid];
        }
    }
    __syncthreads();

    // ---- Phase B1: refilter vs final max; warp wid owns rows wid*16..+15 ----
    for (int rr = 0; rr < 16; ++rr) {
        int mloc = wid * 16 + rr;
        int craw = cnt[mloc];
        bool of  = (craw > SLOTS);
        int base = mloc * SLOTS;
        if (of) {
            if (lane == 0) { int q = atomicAdd(&qn[0], 1); queue[q] = mloc; }
            continue;
        }
        float lim = decf(smax[mloc]) - TH_FINAL;
        bool keep = (lane < craw) && (slot_v[base + lane] >= lim);
        unsigned m = __ballot_sync(0xffffffffu, keep);
        short mycode = keep ? slot_c[base + lane] : 0;
        int pos = __popc(m & ((1u << lane) - 1));
        __syncwarp();
        if (keep) slot_c[base + pos] = mycode;
        __syncwarp();
        int nkeep = __popc(m);
        if (lane == 0) {
            if (nkeep == 1) {
                g_bmu[m0 + mloc] = slot_c[base];
            } else {
                cnt[mloc] = nkeep;
                int q = atomicAdd(&qn[0], 1); queue[q] = mloc;
            }
        }
    }
    __syncthreads();

    // ---- Phase B2: load-balanced exact fp32 rescore of queued rows ----
    int qcount = qn[0];
    for (;;) {
        int t;
        if (lane == 0) t = atomicAdd(&qn[1], 1);
        t = __shfl_sync(0xffffffffu, t, 0);
        if (t >= qcount) break;
        int mloc = queue[t];
        int row  = m0 + mloc;
        int c    = cnt[mloc];
        bool ovf = (c > SLOTS);
        int  lim = ovf ? KCODES : c;
        int base = mloc * SLOTS;

        // gather fp32 x from original NCHW layout (dims lane*8 .. lane*8+7)
        int n = row >> 8, rem = row & 255;
        int ph = rem >> 4, pw = rem & 15;
        int cc = lane >> 1, pyb = (lane & 1) << 1;
        const float* xb = &x[(((n * 16 + cc) * 64 + ph * 4 + pyb) * 64 + pw * 4)];
        float4 x0 = *(const float4*)xb;
        float4 x1 = *(const float4*)(xb + 64);

        float xn = xn_sh[mloc];
        float bv = __int_as_float(0x7f800000);
        int   bi = 0x7fffffff;

        for (int p = 0; p < lim; p += 4) {
            int codes[4];
            float s[4];
            #pragma unroll
            for (int j = 0; j < 4; ++j) {
                int pp = (p + j < lim) ? (p + j) : (lim - 1);
                codes[j] = ovf ? pp : (int)slot_c[base + pp];
            }
            #pragma unroll
            for (int j = 0; j < 4; ++j) {
                float4 c0 = *(const float4*)&cb[codes[j] * DDIM + lane * 8];
                float4 c1 = *(const float4*)&cb[codes[j] * DDIM + lane * 8 + 4];
                float t2 = x0.x * c0.x;
                t2 = fmaf(x0.y, c0.y, t2); t2 = fmaf(x0.z, c0.z, t2); t2 = fmaf(x0.w, c0.w, t2);
                t2 = fmaf(x1.x, c1.x, t2); t2 = fmaf(x1.y, c1.y, t2);
                t2 = fmaf(x1.z, c1.z, t2); t2 = fmaf(x1.w, c1.w, t2);
                s[j] = t2;
            }
            #pragma unroll
            for (int o = 16; o; o >>= 1)
                #pragma unroll
                for (int j = 0; j < 4; ++j)
                    s[j] += __shfl_xor_sync(0xffffffffu, s[j], o);
            #pragma unroll
            for (int j = 0; j < 4; ++j) {
                if (p + j < lim) {
                    float v = __fadd_rn(__fmaf_rn(-2.0f, s[j], xn), g_cnorm[codes[j]]);
                    if (v < bv || (v == bv && codes[j] < bi)) { bv = v; bi = codes[j]; }
                }
            }
        }
        if (lane == 0) g_bmu[row] = bi;
    }
}

// ---------------------------------------------------------------------------
// K2: gather smoothed[bmu] -> output, float4 vectorized (d%4==0 aligned)
// ---------------------------------------------------------------------------
__global__ void k_output(float* __restrict__ out) {
    int e = blockIdx.x * blockDim.x + threadIdx.x;   // one float4 per thread
    int idx = e * 4;
    int w = idx & 63;
    int h = (idx >> 6) & 63;
    int c = (idx >> 12) & 15;
    int n = idx >> 16;
    int i = (n << 8) + ((h >> 2) << 4) + (w >> 2);
    int d = (c << 4) + ((h & 3) << 2);               // w&3 spans the float4
    float4 v = *(const float4*)&g_smooth[g_bmu[i] * DDIM + d];
    *(float4*)&out[idx] = v;
}

// ---------------------------------------------------------------------------
extern "C" void kernel_launch(void* const* d_in, const int* in_sizes, int n_in,
                              void* d_out, int out_size) {
    const float* x  = (const float*)d_in[0];   // (128,16,64,64)
    const float* cb = (const float*)d_in[1];   // (1024,256)
    float* out = (float*)d_out;

    cudaFuncSetAttribute(k_prune, cudaFuncAttributeMaxDynamicSharedMemorySize,
                         SM_TOTAL);

    k_prep  <<<128 + 256, 256>>>(cb);
    k_prune <<<NPATCH / 128, 256, SM_TOTAL>>>(x, cb);
    k_output<<<NPATCH * DDIM / 1024, 256>>>(out);
}

// round 16
// speedup vs baseline: 1.0507x; 1.0507x over previous
#include <cuda_runtime.h>
#include <cuda_bf16.h>
#include <cstdint>

// Problem constants
#define NPATCH   32768      // 128 batch * 16*16 patches
#define DDIM     256        // 16 channels * 4*4 patch
#define KCODES   1024
// 1/(2*variance) with variance = -(256 / (2*ln 0.1))  =>  inv2var = ln(10)/256
#define INV2VAR  0.0089944730195076785f
#define SLOTS    28
#define TH_COLLECT 8e-4f    // collection window vs running max
#define TH_FINAL   5e-4f    // refilter window vs final max

// Scratch (static device globals; no runtime allocation)
__device__ __nv_bfloat16  g_cb16  [KCODES * DDIM];
__device__ float          g_cnorm [KCODES];
__device__ float          g_smooth[KCODES * DDIM];
__device__ int            g_bmu   [NPATCH];

// ---- bit-cast helper ------------------------------------------------------
__device__ __forceinline__ uint32_t bf2_bits(__nv_bfloat162 v) {
    union { __nv_bfloat162 h; uint32_t u; } cv;
    cv.h = v;
    return cv.u;
}

// ---- monotone float<->uint encoding for atomicMax over floats -------------
__device__ __forceinline__ unsigned encf(float f) {
    unsigned u = __float_as_uint(f);
    return (u & 0x80000000u) ? ~u : (u | 0x80000000u);
}
__device__ __forceinline__ float decf(unsigned u) {
    u = (u & 0x80000000u) ? (u & 0x7fffffffu) : ~u;
    return __uint_as_float(u);
}

// ---- tensor-core primitives ----------------------------------------------
__device__ __forceinline__ void ldsm_x4(uint32_t (&r)[4], uint32_t saddr) {
    asm volatile("ldmatrix.sync.aligned.m8n8.x4.shared.b16 {%0,%1,%2,%3}, [%4];"
                 : "=r"(r[0]), "=r"(r[1]), "=r"(r[2]), "=r"(r[3]) : "r"(saddr));
}
__device__ __forceinline__ void mma_bf16(float (&d)[4], const uint32_t (&a)[4],
                                         uint32_t b0, uint32_t b1) {
    asm volatile("mma.sync.aligned.m16n8k16.row.col.f32.bf16.bf16.f32 "
                 "{%0,%1,%2,%3}, {%4,%5,%6,%7}, {%8,%9}, {%0,%1,%2,%3};"
                 : "+f"(d[0]), "+f"(d[1]), "+f"(d[2]), "+f"(d[3])
                 : "r"(a[0]), "r"(a[1]), "r"(a[2]), "r"(a[3]), "r"(b0), "r"(b1));
}

// XOR swizzle for 64B-row smem tiles: chunk' = chunk ^ ((row>>1)&3).
// Conflict-free for LDSM; used consistently on store and load side.
__device__ __forceinline__ uint32_t sw_off(int row, int chunk) {
    return (uint32_t)(row * 64 + ((chunk ^ ((row >> 1) & 3)) << 4));
}

// dynamic-smem layout for k_prune (bytes)
#define SM_XS     0          // [8][128*32] bf16  = 65536
#define SM_CS     65536      // [2][128*32] bf16  = 16384
#define SM_CN     81920      // float[128]     -> 82432
#define SM_MAX    82432      // unsigned[128]  -> 82944
#define SM_CNT    82944      // int[128]       -> 83456
#define SM_SLOTV  83456      // float[128*28] = 14336 -> 97792
#define SM_SLOTC  97792      // short[128*28] =  7168 -> 104960
#define SM_Q      104960     // int[128]       -> 105472
#define SM_QN     105472     // int[2] (qcount, qhead)
#define SM_XN     105480     // float[128] xnorm -> 105992
#define SM_TOTAL  106112

// ---------------------------------------------------------------------------
// K0: codebook prep.
// Blocks [0,128): cnorm + bf16 copy (one warp per row).
// Blocks [128,384): Gaussian-smoothed codebook (4 rows/block, radius-64),
//   unrolled x4 for memory-level parallelism.
// ---------------------------------------------------------------------------
__global__ void k_prep(const float* __restrict__ cb) {
    int tid = threadIdx.x;
    if (blockIdx.x < 128) {
        int row  = blockIdx.x * 8 + (tid >> 5);
        int lane = tid & 31;
        const float* p = cb + row * DDIM;
        float s = 0.0f;
        #pragma unroll
        for (int j = 0; j < DDIM / 32; ++j) {
            float v = p[lane + j * 32];
            g_cb16[row * DDIM + lane + j * 32] = __float2bfloat16(v);
            s = fmaf(v, v, s);
        }
        #pragma unroll
        for (int o = 16; o; o >>= 1) s += __shfl_xor_sync(0xffffffffu, s, o);
        if (lane == 0) g_cnorm[row] = s;
    } else {
        __shared__ float wd[136];
        int jbase = (blockIdx.x - 128) * 4;
        if (tid < 136) {
            float dd = (float)(tid - 67);
            wd[tid] = expf(-(dd * dd) * INV2VAR);
        }
        __syncthreads();
        float acc[4] = {0.f, 0.f, 0.f, 0.f};
        int klo = jbase - 64;      if (klo < 0) klo = 0;
        int khi = jbase + 3 + 64;  if (khi > KCODES - 1) khi = KCODES - 1;
        int kk = klo;
        for (; kk + 3 <= khi; kk += 4) {       // 4 loads in flight
            float v0 = cb[(kk + 0) * DDIM + tid];
            float v1 = cb[(kk + 1) * DDIM + tid];
            float v2 = cb[(kk + 2) * DDIM + tid];
            float v3 = cb[(kk + 3) * DDIM + tid];
            int b0 = kk - jbase + 67;
            #pragma unroll
            for (int t = 0; t < 4; ++t) {
                float a = acc[t];
                a = fmaf(wd[b0 - t],     v0, a);
                a = fmaf(wd[b0 + 1 - t], v1, a);
                a = fmaf(wd[b0 + 2 - t], v2, a);
                a = fmaf(wd[b0 + 3 - t], v3, a);
                acc[t] = a;
            }
        }
        for (; kk <= khi; ++kk) {
            float v = cb[kk * DDIM + tid];
            int base = kk - jbase + 67;
            #pragma unroll
            for (int t = 0; t < 4; ++t)
                acc[t] = fmaf(wd[base - t], v, acc[t]);
        }
        #pragma unroll
        for (int t = 0; t < 4; ++t)
            g_smooth[(jbase + t) * DDIM + tid] = acc[t];
    }
}

// ---------------------------------------------------------------------------
// K1: fused patchify + prune + refilter + exact rescore (R13 configuration:
// reg-staged double-buffered C stream, barrier'd epilogue — measured best).
// ---------------------------------------------------------------------------
__global__ __launch_bounds__(256, 2) void k_prune(const float* __restrict__ x,
                                                  const float* __restrict__ cb) {
    extern __shared__ char smem_raw[];
    __nv_bfloat16* Xs    = (__nv_bfloat16*)(smem_raw + SM_XS);
    __nv_bfloat16* Cs    = (__nv_bfloat16*)(smem_raw + SM_CS);
    float*    cn_sh  = (float*)   (smem_raw + SM_CN);
    unsigned* smax   = (unsigned*)(smem_raw + SM_MAX);
    int*      cnt    = (int*)     (smem_raw + SM_CNT);
    float*    slot_v = (float*)   (smem_raw + SM_SLOTV);
    short*    slot_c = (short*)   (smem_raw + SM_SLOTC);
    int*      queue  = (int*)     (smem_raw + SM_Q);
    int*      qn     = (int*)     (smem_raw + SM_QN);   // [0]=count, [1]=head
    float*    xn_sh  = (float*)   (smem_raw + SM_XN);

    int tid  = threadIdx.x;
    int lane = tid & 31;
    int wid  = tid >> 5;
    int wm   = wid & 3;            // m band: 32 rows
    int wn   = wid >> 2;           // n band: 64 codes
    int m0   = blockIdx.x * 128;

    if (tid < 128) { smax[tid] = 0u; cnt[tid] = 0; cn_sh[tid] = g_cnorm[tid]; }
    if (tid == 0) { qn[0] = 0; qn[1] = 0; }

    uint32_t xs_base = (uint32_t)__cvta_generic_to_shared(Xs);
    uint32_t cs_base = (uint32_t)__cvta_generic_to_shared(Cs);

    // ---- fused patchify: x fp32 -> bf16 Xs + xnorm. Per iteration i, each
    // warp owns one whole row (row = i*8 + wid), lane = 16B chunk (8 dims).
    #pragma unroll
    for (int i = 0; i < 16; ++i) {
        int row = i * 8 + wid;
        int m   = m0 + row;
        int n = m >> 8, rem = m & 255;
        int ph = rem >> 4, pw = rem & 15;
        int c = lane >> 1, pyb = (lane & 1) << 1;      // dims lane*8 .. +7
        const float* xb = &x[(((n * 16 + c) * 64 + ph * 4 + pyb) * 64 + pw * 4)];
        float4 a = *(const float4*)xb;
        float4 b = *(const float4*)(xb + 64);
        uint4 pk;
        pk.x = bf2_bits(__floats2bfloat162_rn(a.x, a.y));
        pk.y = bf2_bits(__floats2bfloat162_rn(a.z, a.w));
        pk.z = bf2_bits(__floats2bfloat162_rn(b.x, b.y));
        pk.w = bf2_bits(__floats2bfloat162_rn(b.z, b.w));
        int slab = lane >> 2, chunk = lane & 3;
        *(uint4*)((char*)Xs + slab * 8192 + sw_off(row, chunk)) = pk;
        float s = fmaf(a.x, a.x, fmaf(a.y, a.y, fmaf(a.z, a.z, a.w * a.w)));
        s = fmaf(b.x, b.x, fmaf(b.y, b.y, fmaf(b.z, b.z, fmaf(b.w, b.w, s))));
        #pragma unroll
        for (int o = 16; o; o >>= 1) s += __shfl_xor_sync(0xffffffffu, s, o);
        if (lane == 0) xn_sh[row] = s;
    }

    // ---- C streaming: 2 chunks (16B) per thread per slab ----
    int r0 = tid >> 2,  g0 = tid & 3;
    int r1 = r0 + 64;
    uint32_t so0 = sw_off(r0, g0), so1 = sw_off(r1, g0);

    uint4 pc0, pc1;
    auto glob_loadC = [&](int ls) {
        int k0 = (ls & 7) * 32;
        int n0 = (ls >> 3) << 7;
        pc0 = *(const uint4*)&g_cb16[(n0 + r0) * DDIM + k0 + g0 * 8];
        pc1 = *(const uint4*)&g_cb16[(n0 + r1) * DDIM + k0 + g0 * 8];
    };
    auto stsC = [&](int buf) {
        *(uint4*)((char*)Cs + buf * 8192 + so0) = pc0;
        *(uint4*)((char*)Cs + buf * 8192 + so1) = pc1;
    };

    // LDSM invariants
    int arow[2], brow[4];
    #pragma unroll
    for (int mt = 0; mt < 2; ++mt) arow[mt] = wm * 32 + mt * 16 + (lane & 15);
    #pragma unroll
    for (int nt = 0; nt < 4; ++nt) brow[nt] = wn * 64 + nt * 16 + (lane & 15);
    int ch_hi = lane >> 4;

    float acc[2][8][4];
    glob_loadC(0);
    stsC(0);
    glob_loadC(1);

    for (int ls = 0; ls < 64; ++ls) {
        int s   = ls & 7;
        int buf = ls & 1;
        if (ls > 0) stsC(buf);
        __syncthreads();               // publish slab ls (and X on ls==0)
        if (s == 0) {
            #pragma unroll
            for (int nt = 0; nt < 8; ++nt)
                #pragma unroll
                for (int z = 0; z < 4; ++z) {
                    int nloc = wn * 64 + nt * 8 + 2 * (lane & 3) + (z & 1);
                    float v = -0.5f * cn_sh[nloc];
                    acc[0][nt][z] = v;
                    acc[1][nt][z] = v;
                }
        }
        if (ls < 63) glob_loadC(ls + 1);

        uint32_t xslab = xs_base + (uint32_t)(s * 8192);
        #pragma unroll
        for (int kstep = 0; kstep < 2; ++kstep) {
            int kc = kstep * 2 + ch_hi;
            uint32_t a[2][4];
            #pragma unroll
            for (int mt = 0; mt < 2; ++mt)
                ldsm_x4(a[mt], xslab + sw_off(arow[mt], kc));
            #pragma unroll
            for (int ntp = 0; ntp < 4; ++ntp) {
                uint32_t b[4];
                ldsm_x4(b, cs_base + (uint32_t)(buf * 8192) + sw_off(brow[ntp], kc));
                #pragma unroll
                for (int mt = 0; mt < 2; ++mt) {
                    mma_bf16(acc[mt][2 * ntp + 0], a[mt], b[0], b[2]);
                    mma_bf16(acc[mt][2 * ntp + 1], a[mt], b[1], b[3]);
                }
            }
        }

        if (s == 7) {
            int nchunk0 = (ls >> 3) << 7;
            // running max update
            #pragma unroll
            for (int mt = 0; mt < 2; ++mt)
                #pragma unroll
                for (int h = 0; h < 2; ++h) {
                    int mloc = wm * 32 + mt * 16 + (lane >> 2) + 8 * h;
                    float mv = acc[mt][0][2 * h];
                    #pragma unroll
                    for (int nt = 0; nt < 8; ++nt) {
                        mv = fmaxf(mv, acc[mt][nt][2 * h + 0]);
                        mv = fmaxf(mv, acc[mt][nt][2 * h + 1]);
                    }
                    mv = fmaxf(mv, __shfl_xor_sync(0xffffffffu, mv, 1));
                    mv = fmaxf(mv, __shfl_xor_sync(0xffffffffu, mv, 2));
                    if ((lane & 3) == 0) atomicMax(&smax[mloc], encf(mv));
                }
            __syncthreads();
            // collect (value, code) within TH_COLLECT of running max
            #pragma unroll
            for (int mt = 0; mt < 2; ++mt)
                #pragma unroll
                for (int h = 0; h < 2; ++h) {
                    int mloc = wm * 32 + mt * 16 + (lane >> 2) + 8 * h;
                    float lim = decf(smax[mloc]) - TH_COLLECT;
                    #pragma unroll
                    for (int nt = 0; nt < 8; ++nt)
                        #pragma unroll
                        for (int col = 0; col < 2; ++col) {
                            float v = acc[mt][nt][2 * h + col];
                            if (v >= lim) {
                                int code = nchunk0 + wn * 64 + nt * 8 + 2 * (lane & 3) + col;
                                int p = atomicAdd(&cnt[mloc], 1);
                                if (p < SLOTS) {
                                    slot_v[mloc * SLOTS + p] = v;
                                    slot_c[mloc * SLOTS + p] = (short)code;
                                }
                            }
                        }
                }
            // prefetch next chunk's cnorm (ordered by next top-of-loop sync)
            if (ls < 63 && tid < 128) cn_sh[tid] = g_cnorm[nchunk0 + 128 + tid];
        }
    }
    __syncthreads();

    // ---- Phase B1: refilter vs final max; warp wid owns rows wid*16..+15 ----
    for (int rr = 0; rr < 16; ++rr) {
        int mloc = wid * 16 + rr;
        int craw = cnt[mloc];
        bool of  = (craw > SLOTS);
        int base = mloc * SLOTS;
        if (of) {
            if (lane == 0) { int q = atomicAdd(&qn[0], 1); queue[q] = mloc; }
            continue;
        }
        float lim = decf(smax[mloc]) - TH_FINAL;
        bool keep = (lane < craw) && (slot_v[base + lane] >= lim);
        unsigned m = __ballot_sync(0xffffffffu, keep);
        short mycode = keep ? slot_c[base + lane] : 0;
        int pos = __popc(m & ((1u << lane) - 1));
        __syncwarp();
        if (keep) slot_c[base + pos] = mycode;
        __syncwarp();
        int nkeep = __popc(m);
        if (lane == 0) {
            if (nkeep == 1) {
                g_bmu[m0 + mloc] = slot_c[base];
            } else {
                cnt[mloc] = nkeep;
                int q = atomicAdd(&qn[0], 1); queue[q] = mloc;
            }
        }
    }
    __syncthreads();

    // ---- Phase B2: load-balanced exact fp32 rescore of queued rows ----
    int qcount = qn[0];
    for (;;) {
        int t;
        if (lane == 0) t = atomicAdd(&qn[1], 1);
        t = __shfl_sync(0xffffffffu, t, 0);
        if (t >= qcount) break;
        int mloc = queue[t];
        int row  = m0 + mloc;
        int c    = cnt[mloc];
        bool ovf = (c > SLOTS);
        int  lim = ovf ? KCODES : c;
        int base = mloc * SLOTS;

        // gather fp32 x from original NCHW layout (dims lane*8 .. lane*8+7)
        int n = row >> 8, rem = row & 255;
        int ph = rem >> 4, pw = rem & 15;
        int cc = lane >> 1, pyb = (lane & 1) << 1;
        const float* xb = &x[(((n * 16 + cc) * 64 + ph * 4 + pyb) * 64 + pw * 4)];
        float4 x0 = *(const float4*)xb;
        float4 x1 = *(const float4*)(xb + 64);

        float xn = xn_sh[mloc];
        float bv = __int_as_float(0x7f800000);
        int   bi = 0x7fffffff;

        for (int p = 0; p < lim; p += 4) {
            int codes[4];
            float s[4];
            #pragma unroll
            for (int j = 0; j < 4; ++j) {
                int pp = (p + j < lim) ? (p + j) : (lim - 1);
                codes[j] = ovf ? pp : (int)slot_c[base + pp];
            }
            #pragma unroll
            for (int j = 0; j < 4; ++j) {
                float4 c0 = *(const float4*)&cb[codes[j] * DDIM + lane * 8];
                float4 c1 = *(const float4*)&cb[codes[j] * DDIM + lane * 8 + 4];
                float t2 = x0.x * c0.x;
                t2 = fmaf(x0.y, c0.y, t2); t2 = fmaf(x0.z, c0.z, t2); t2 = fmaf(x0.w, c0.w, t2);
                t2 = fmaf(x1.x, c1.x, t2); t2 = fmaf(x1.y, c1.y, t2);
                t2 = fmaf(x1.z, c1.z, t2); t2 = fmaf(x1.w, c1.w, t2);
                s[j] = t2;
            }
            #pragma unroll
            for (int o = 16; o; o >>= 1)
                #pragma unroll
                for (int j = 0; j < 4; ++j)
                    s[j] += __shfl_xor_sync(0xffffffffu, s[j], o);
            #pragma unroll
            for (int j = 0; j < 4; ++j) {
                if (p + j < lim) {
                    float v = __fadd_rn(__fmaf_rn(-2.0f, s[j], xn), g_cnorm[codes[j]]);
                    if (v < bv || (v == bv && codes[j] < bi)) { bv = v; bi = codes[j]; }
                }
            }
        }
        if (lane == 0) g_bmu[row] = bi;
    }
}

// ---------------------------------------------------------------------------
// K2: gather smoothed[bmu] -> output, float4 vectorized (d%4==0 aligned)
// ---------------------------------------------------------------------------
__global__ void k_output(float* __restrict__ out) {
    int e = blockIdx.x * blockDim.x + threadIdx.x;   // one float4 per thread
    int idx = e * 4;
    int w = idx & 63;
    int h = (idx >> 6) & 63;
    int c = (idx >> 12) & 15;
    int n = idx >> 16;
    int i = (n << 8) + ((h >> 2) << 4) + (w >> 2);
    int d = (c << 4) + ((h & 3) << 2);               // w&3 spans the float4
    float4 v = *(const float4*)&g_smooth[g_bmu[i] * DDIM + d];
    *(float4*)&out[idx] = v;
}

// ---------------------------------------------------------------------------
extern "C" void kernel_launch(void* const* d_in, const int* in_sizes, int n_in,
                              void* d_out, int out_size) {
    const float* x  = (const float*)d_in[0];   // (128,16,64,64)
    const float* cb = (const float*)d_in[1];   // (1024,256)
    float* out = (float*)d_out;

    cudaFuncSetAttribute(k_prune, cudaFuncAttributeMaxDynamicSharedMemorySize,
                         SM_TOTAL);

    k_prep  <<<128 + 256, 256>>>(cb);
    k_prune <<<NPATCH / 128, 256, SM_TOTAL>>>(x, cb);
    k_output<<<NPATCH * DDIM / 1024, 256>>>(out);
}